// round 14
// baseline (speedup 1.0000x reference)
#include <cuda_runtime.h>
#include <cuda_fp16.h>
#include <math.h>
#include <float.h>
#include <cstdint>

#define BB 8
#define EE 2048
#define DD 512
#define DA 64

typedef unsigned long long ull;

// Scratch (static __device__ arrays: allocation-guard safe)
__device__ float g_q[BB * EE * DD];
__device__ float g_k[BB * EE * DD];
__device__ float g_v[BB * EE * DD];
__device__ float g_s[(size_t)BB * EE * EE];
__device__ __half g_s16[(size_t)BB * EE * EE];   // fp16 attn probs
__device__ __half g_vt16[(size_t)BB * DD * EE];  // fp16 V^T, [b][n][k]
__device__ __half g_q16[BB * EE * DD];           // fp16 q (HMMA scores operand)
__device__ __half g_k16[BB * EE * DD];           // fp16 k

// smem XOR swizzle for SIMT GEMM tiles
#define SW(r) ((((r) >> 2) & 3) << 3)
// SW128 byte swizzle for 128B-row fp16 tiles (16B-granular)
#define SW128B(o) ((o) ^ (((o) >> 3) & 0x70))

// ---------------------------------------------------------------------------
// helpers
// ---------------------------------------------------------------------------
__device__ __forceinline__ ull pk2(float lo, float hi) {
    ull r;
    asm("mov.b64 %0, {%1,%2};" : "=l"(r) : "f"(lo), "f"(hi));
    return r;
}
__device__ __forceinline__ void ffma2(ull& c, ull a, ull b) {
    asm("fma.rn.f32x2 %0, %1, %2, %0;" : "+l"(c) : "l"(a), "l"(b));
}
__device__ __forceinline__ float2 upk2(ull v) {
    float2 f;
    asm("mov.b64 {%0,%1}, %2;" : "=f"(f.x), "=f"(f.y) : "l"(v));
    return f;
}
__device__ __forceinline__ uint32_t smem_u32(const void* p) {
    uint32_t a;
    asm("{ .reg .u64 t; cvta.to.shared.u64 t, %1; cvt.u32.u64 %0, t; }"
        : "=r"(a) : "l"(p));
    return a;
}
__device__ __forceinline__ void ldm_x4(uint32_t* r, uint32_t addr) {
    asm volatile(
        "ldmatrix.sync.aligned.m8n8.x4.shared.b16 {%0,%1,%2,%3}, [%4];"
        : "=r"(r[0]), "=r"(r[1]), "=r"(r[2]), "=r"(r[3]) : "r"(addr));
}
__device__ __forceinline__ void mma16816(float* d, const uint32_t* a, const uint32_t* b) {
    asm volatile(
        "mma.sync.aligned.m16n8k16.row.col.f32.f16.f16.f32 "
        "{%0,%1,%2,%3}, {%4,%5,%6,%7}, {%8,%9}, {%0,%1,%2,%3};"
        : "+f"(d[0]), "+f"(d[1]), "+f"(d[2]), "+f"(d[3])
        : "r"(a[0]), "r"(a[1]), "r"(a[2]), "r"(a[3]), "r"(b[0]), "r"(b[1]));
}
__device__ __forceinline__ void cp16(uint32_t saddr, const void* gptr) {
    asm volatile("cp.async.cg.shared.global [%0], [%1], 16;"
                 :: "r"(saddr), "l"(gptr) : "memory");
}
__device__ __forceinline__ uint2 h4(float4 v) {
    __half2 a = __floats2half2_rn(v.x, v.y);
    __half2 b = __floats2half2_rn(v.z, v.w);
    uint2 r;
    r.x = *(uint32_t*)&a;
    r.y = *(uint32_t*)&b;
    return r;
}

// fp32 rescue dot (rare, near-threshold elements only)
__device__ __noinline__ float dot512(const float* __restrict__ a,
                                     const float* __restrict__ b) {
    float s = 0.f;
#pragma unroll 8
    for (int k = 0; k < DD; k += 4) {
        float4 x = *(const float4*)(a + k);
        float4 y = *(const float4*)(b + k);
        s += x.x * y.x + x.y * y.y + x.z * y.z + x.w * y.w;
    }
    return s;
}

// ---------------------------------------------------------------------------
// SIMT 128x128 tile GEMM core (f32x2), double-buffered + swizzled (proven)
// ---------------------------------------------------------------------------
template <bool BT>
__device__ __forceinline__ void mm_tile(
    const float* __restrict__ A, int lda,
    const float* __restrict__ B, int ldb,
    int Ktot, float (*As)[16][128], float (*Bs)[16][128], ull acc[4][8])
{
    const int t = threadIdx.x;
    const int a_c4 = (t & 3) << 2;
    const int a_r  = t >> 2;
    const int b_n4 = (t & 31) << 2;
    const int b_k  = t >> 5;
    const int tx = t & 15, ty = t >> 4;
    const int xsa = a_r ^ SW(a_c4);
    const int xb0 = b_n4 ^ SW(b_k);
    const int xb1 = b_n4 ^ SW(b_k + 8);

    float4 ra0, ra1, rb0, rb1;

    ra0 = *(const float4*)(A + (size_t)a_r * lda + a_c4);
    ra1 = *(const float4*)(A + (size_t)(a_r + 64) * lda + a_c4);
    if (BT) {
        rb0 = *(const float4*)(B + (size_t)a_r * ldb + a_c4);
        rb1 = *(const float4*)(B + (size_t)(a_r + 64) * ldb + a_c4);
    } else {
        rb0 = *(const float4*)(B + (size_t)b_k * ldb + b_n4);
        rb1 = *(const float4*)(B + (size_t)(b_k + 8) * ldb + b_n4);
    }

    int buf = 0;
    {
        As[0][a_c4 + 0][xsa] = ra0.x; As[0][a_c4 + 1][xsa] = ra0.y;
        As[0][a_c4 + 2][xsa] = ra0.z; As[0][a_c4 + 3][xsa] = ra0.w;
        As[0][a_c4 + 0][xsa + 64] = ra1.x; As[0][a_c4 + 1][xsa + 64] = ra1.y;
        As[0][a_c4 + 2][xsa + 64] = ra1.z; As[0][a_c4 + 3][xsa + 64] = ra1.w;
        if (BT) {
            Bs[0][a_c4 + 0][xsa] = rb0.x; Bs[0][a_c4 + 1][xsa] = rb0.y;
            Bs[0][a_c4 + 2][xsa] = rb0.z; Bs[0][a_c4 + 3][xsa] = rb0.w;
            Bs[0][a_c4 + 0][xsa + 64] = rb1.x; Bs[0][a_c4 + 1][xsa + 64] = rb1.y;
            Bs[0][a_c4 + 2][xsa + 64] = rb1.z; Bs[0][a_c4 + 3][xsa + 64] = rb1.w;
        } else {
            *(float4*)&Bs[0][b_k][xb0] = rb0;
            *(float4*)&Bs[0][b_k + 8][xb1] = rb1;
        }
    }
    __syncthreads();

    for (int k0 = 0; k0 < Ktot; k0 += 16) {
        const bool more = (k0 + 16) < Ktot;
        if (more) {
            int kn = k0 + 16;
            ra0 = *(const float4*)(A + (size_t)a_r * lda + kn + a_c4);
            ra1 = *(const float4*)(A + (size_t)(a_r + 64) * lda + kn + a_c4);
            if (BT) {
                rb0 = *(const float4*)(B + (size_t)a_r * ldb + kn + a_c4);
                rb1 = *(const float4*)(B + (size_t)(a_r + 64) * ldb + kn + a_c4);
            } else {
                rb0 = *(const float4*)(B + (size_t)(kn + b_k) * ldb + b_n4);
                rb1 = *(const float4*)(B + (size_t)(kn + b_k + 8) * ldb + b_n4);
            }
        }
#pragma unroll
        for (int kk = 0; kk < 16; kk++) {
            const int xr = SW(kk);
            ulonglong2 ap0 = *(const ulonglong2*)&As[buf][kk][(ty << 2) ^ xr];
            ulonglong2 ap1 = *(const ulonglong2*)&As[buf][kk][64 + ((ty << 2) ^ xr)];
            float4 b0 = *(const float4*)&Bs[buf][kk][(tx << 2) ^ xr];
            float4 b1 = *(const float4*)&Bs[buf][kk][64 + ((tx << 2) ^ xr)];
            ull bb[8] = {pk2(b0.x, b0.x), pk2(b0.y, b0.y),
                         pk2(b0.z, b0.z), pk2(b0.w, b0.w),
                         pk2(b1.x, b1.x), pk2(b1.y, b1.y),
                         pk2(b1.z, b1.z), pk2(b1.w, b1.w)};
            ull aa[4] = {ap0.x, ap0.y, ap1.x, ap1.y};
#pragma unroll
            for (int rp = 0; rp < 4; rp++)
#pragma unroll
                for (int j = 0; j < 8; j++) ffma2(acc[rp][j], aa[rp], bb[j]);
        }
        if (more) {
            int nb = buf ^ 1;
            As[nb][a_c4 + 0][xsa] = ra0.x; As[nb][a_c4 + 1][xsa] = ra0.y;
            As[nb][a_c4 + 2][xsa] = ra0.z; As[nb][a_c4 + 3][xsa] = ra0.w;
            As[nb][a_c4 + 0][xsa + 64] = ra1.x; As[nb][a_c4 + 1][xsa + 64] = ra1.y;
            As[nb][a_c4 + 2][xsa + 64] = ra1.z; As[nb][a_c4 + 3][xsa + 64] = ra1.w;
            if (BT) {
                Bs[nb][a_c4 + 0][xsa] = rb0.x; Bs[nb][a_c4 + 1][xsa] = rb0.y;
                Bs[nb][a_c4 + 2][xsa] = rb0.z; Bs[nb][a_c4 + 3][xsa] = rb0.w;
                Bs[nb][a_c4 + 0][xsa + 64] = rb1.x; Bs[nb][a_c4 + 1][xsa + 64] = rb1.y;
                Bs[nb][a_c4 + 2][xsa + 64] = rb1.z; Bs[nb][a_c4 + 3][xsa + 64] = rb1.w;
            } else {
                *(float4*)&Bs[nb][b_k][xb0] = rb0;
                *(float4*)&Bs[nb][b_k + 8][xb1] = rb1;
            }
        }
        __syncthreads();
        buf ^= 1;
    }
}

__device__ __forceinline__ int pair_row(int rp, int ty) {
    return ((rp >> 1) << 6) + (ty << 2) + ((rp & 1) << 1);
}

// ---------------------------------------------------------------------------
// Kernel 1: MERGED proj + aux-scores (1-D grid).  proj also emits fp16 q/k.
// ---------------------------------------------------------------------------
__global__ void __launch_bounds__(256, 2) proj_aux_kernel(
    const float* __restrict__ x,
    const float* __restrict__ Wq, const float* __restrict__ bq,
    const float* __restrict__ Wk, const float* __restrict__ bk,
    const float* __restrict__ Wv, const float* __restrict__ bv,
    const float* __restrict__ qa, const float* __restrict__ ka)
{
    __shared__ __align__(16) float As[2][16][128];
    __shared__ __align__(16) float Bs[2][16][128];

    int bid = blockIdx.x;
    int tx = threadIdx.x & 15, ty = threadIdx.x >> 4;

    if (bid < 1536) {
        int nx = bid & 3, my = (bid >> 2) & 15, zb = bid >> 6;
        int b = zb / 3, p = zb % 3;
        const float* W    = (p == 0) ? Wq : (p == 1) ? Wk : Wv;
        const float* bias = (p == 0) ? bq : (p == 1) ? bk : bv;
        float* out = ((p == 0) ? g_q : (p == 1) ? g_k : g_v) + (size_t)b * EE * DD;
        __half* out16 = (p == 0) ? (g_q16 + (size_t)b * EE * DD)
                       : (p == 1) ? (g_k16 + (size_t)b * EE * DD) : (__half*)0;

        int m0 = my * 128, n0 = nx * 128;

        ull acc[4][8];
#pragma unroll
        for (int i = 0; i < 4; i++)
#pragma unroll
            for (int j = 0; j < 8; j++) acc[i][j] = 0ull;

        mm_tile<false>(x + (size_t)b * EE * DD + (size_t)m0 * DD, DD,
                       W + n0, DD, DD, As, Bs, acc);

        float4 bias0 = *(const float4*)(bias + n0 + (tx << 2));
        float4 bias1 = *(const float4*)(bias + n0 + 64 + (tx << 2));
        float bb0[4] = {bias0.x, bias0.y, bias0.z, bias0.w};
        float bb1[4] = {bias1.x, bias1.y, bias1.z, bias1.w};
#pragma unroll
        for (int rp = 0; rp < 4; rp++) {
            int r = m0 + pair_row(rp, ty);
            float2 c[8];
#pragma unroll
            for (int j = 0; j < 8; j++) c[j] = upk2(acc[rp][j]);
            float4 lo0 = {c[0].x + bb0[0], c[1].x + bb0[1], c[2].x + bb0[2], c[3].x + bb0[3]};
            float4 lo1 = {c[4].x + bb1[0], c[5].x + bb1[1], c[6].x + bb1[2], c[7].x + bb1[3]};
            float4 hi0 = {c[0].y + bb0[0], c[1].y + bb0[1], c[2].y + bb0[2], c[3].y + bb0[3]};
            float4 hi1 = {c[4].y + bb1[0], c[5].y + bb1[1], c[6].y + bb1[2], c[7].y + bb1[3]};
            *(float4*)(out + (size_t)r * DD + n0 + (tx << 2)) = lo0;
            *(float4*)(out + (size_t)r * DD + n0 + 64 + (tx << 2)) = lo1;
            *(float4*)(out + (size_t)(r + 1) * DD + n0 + (tx << 2)) = hi0;
            *(float4*)(out + (size_t)(r + 1) * DD + n0 + 64 + (tx << 2)) = hi1;
            if (out16) {
                *(uint2*)(out16 + (size_t)r * DD + n0 + (tx << 2)) = h4(lo0);
                *(uint2*)(out16 + (size_t)r * DD + n0 + 64 + (tx << 2)) = h4(lo1);
                *(uint2*)(out16 + (size_t)(r + 1) * DD + n0 + (tx << 2)) = h4(hi0);
                *(uint2*)(out16 + (size_t)(r + 1) * DD + n0 + 64 + (tx << 2)) = h4(hi1);
            }
        }
    } else {
        int a = bid - 1536;
        int fx = a & 15, fy = (a >> 4) & 15, b = a >> 8;
        int m0 = fy * 128, n0 = fx * 128;

        ull acc[4][8];
#pragma unroll
        for (int i = 0; i < 4; i++)
#pragma unroll
            for (int j = 0; j < 8; j++) acc[i][j] = 0ull;

        mm_tile<true>(qa + (size_t)b * EE * DA + (size_t)m0 * DA, DA,
                      ka + (size_t)b * EE * DA + (size_t)n0 * DA, DA,
                      DA, As, Bs, acc);

        float* S = g_s + (size_t)b * EE * EE;
#pragma unroll
        for (int rp = 0; rp < 4; rp++) {
            int r = m0 + pair_row(rp, ty);
            float2 c[8];
#pragma unroll
            for (int j = 0; j < 8; j++) c[j] = upk2(acc[rp][j]);
            float4 lo0 = {c[0].x * 0.125f, c[1].x * 0.125f, c[2].x * 0.125f, c[3].x * 0.125f};
            float4 lo1 = {c[4].x * 0.125f, c[5].x * 0.125f, c[6].x * 0.125f, c[7].x * 0.125f};
            float4 hi0 = {c[0].y * 0.125f, c[1].y * 0.125f, c[2].y * 0.125f, c[3].y * 0.125f};
            float4 hi1 = {c[4].y * 0.125f, c[5].y * 0.125f, c[6].y * 0.125f, c[7].y * 0.125f};
            *(float4*)(S + (size_t)r * EE + n0 + (tx << 2)) = lo0;
            *(float4*)(S + (size_t)r * EE + n0 + 64 + (tx << 2)) = lo1;
            *(float4*)(S + (size_t)(r + 1) * EE + n0 + (tx << 2)) = hi0;
            *(float4*)(S + (size_t)(r + 1) * EE + n0 + 64 + (tx << 2)) = hi1;
        }
    }
}

// ---------------------------------------------------------------------------
// Kernel 1b: V transpose + fp16 convert.  g_v[b][k][n] -> g_vt16[b][n][k]
// ---------------------------------------------------------------------------
__global__ void __launch_bounds__(256) vt_kernel()
{
    __shared__ float tile[32][33];
    int b = blockIdx.z;
    int n0 = blockIdx.x * 32, k0 = blockIdx.y * 32;
    int tx = threadIdx.x & 31, ty = threadIdx.x >> 5;
    const float* V = g_v + (size_t)b * EE * DD;
    __half* VT = g_vt16 + (size_t)b * DD * EE;
#pragma unroll
    for (int i = 0; i < 4; i++)
        tile[ty + i * 8][tx] = V[(size_t)(k0 + ty + i * 8) * DD + n0 + tx];
    __syncthreads();
#pragma unroll
    for (int i = 0; i < 4; i++)
        VT[(size_t)(n0 + ty + i * 8) * EE + k0 + tx] =
            __float2half_rn(tile[tx][ty + i * 8]);
}

// ---------------------------------------------------------------------------
// Kernel 2: main scores via fp16 HMMA (cp.async pipeline) + fp32 rescue
// near threshold + blend + adjacency mask.
// A = g_q16[m][k], B = g_k16[n][k] (both K-major), K = 512.
// grid (16, 16, 8), 256 threads, 64 KB dynamic smem.
// ---------------------------------------------------------------------------
__global__ void __launch_bounds__(256) scores_hmma_kernel(
    const int* __restrict__ adj, const float* __restrict__ mc,
    const float* __restrict__ thr_p)
{
    extern __shared__ __align__(16) __half dynsm[];

    const int tid = threadIdx.x;
    const int w = tid >> 5, lane = tid & 31;
    const int wm = w & 1, wn = w >> 1;
    const int b = blockIdx.z;
    const int m0 = blockIdx.y * 128, n0 = blockIdx.x * 128;

    const __half* Ag = g_q16 + (size_t)b * EE * DD + (size_t)m0 * DD;
    const __half* Bg = g_k16 + (size_t)b * EE * DD + (size_t)n0 * DD;

    const uint32_t base = smem_u32(dynsm);

    float acc[4][4][4];
#pragma unroll
    for (int mt = 0; mt < 4; mt++)
#pragma unroll
        for (int nt = 0; nt < 4; nt++)
#pragma unroll
            for (int q = 0; q < 4; q++) acc[mt][nt][q] = 0.f;

    const int lr = tid >> 1;
    const int lu = (tid & 1) * 4;

    const int a_m  = lane & 15;
    const int a_k8 = (lane >> 4) & 1;
    const int b_n  = ((lane >> 4) & 1) * 8 + (lane & 7);
    const int b_k8 = (lane >> 3) & 1;

    auto issue = [&](int k0, int bf) {
        uint32_t sa = base + bf * 32768u;
        uint32_t sb = sa + 16384u;
#pragma unroll
        for (int i = 0; i < 4; i++) {
            int u = lu + i;
            uint32_t off = SW128B((uint32_t)(lr * 128 + u * 16));
            cp16(sa + off, Ag + (size_t)lr * DD + k0 + u * 8);
            cp16(sb + off, Bg + (size_t)lr * DD + k0 + u * 8);
        }
        asm volatile("cp.async.commit_group;" ::: "memory");
    };

    issue(0, 0);
    int bf = 0;

    for (int k0 = 0; k0 < DD; k0 += 64) {
        const bool more = (k0 + 64) < DD;
        if (more) {
            issue(k0 + 64, bf ^ 1);
            asm volatile("cp.async.wait_group 1;" ::: "memory");
        } else {
            asm volatile("cp.async.wait_group 0;" ::: "memory");
        }
        __syncthreads();

        const uint32_t sA_a = base + bf * 32768u;
        const uint32_t sB_a = sA_a + 16384u;
#pragma unroll
        for (int ks = 0; ks < 4; ks++) {
            uint32_t afr[4][4];
#pragma unroll
            for (int mt = 0; mt < 4; mt++) {
                uint32_t off = SW128B((uint32_t)(
                    (wm * 64 + mt * 16 + a_m) * 128 + (ks * 16 + a_k8 * 8) * 2));
                ldm_x4(afr[mt], sA_a + off);
            }
            uint32_t bfr[4][2];
            {
                uint32_t off0 = SW128B((uint32_t)(
                    (wn * 32 + b_n) * 128 + (ks * 16 + b_k8 * 8) * 2));
                uint32_t r[4];
                ldm_x4(r, sB_a + off0);
                bfr[0][0] = r[0]; bfr[0][1] = r[1];
                bfr[1][0] = r[2]; bfr[1][1] = r[3];
                uint32_t off1 = SW128B((uint32_t)(
                    (wn * 32 + 16 + b_n) * 128 + (ks * 16 + b_k8 * 8) * 2));
                ldm_x4(r, sB_a + off1);
                bfr[2][0] = r[0]; bfr[2][1] = r[1];
                bfr[3][0] = r[2]; bfr[3][1] = r[3];
            }
#pragma unroll
            for (int mt = 0; mt < 4; mt++)
#pragma unroll
                for (int nt = 0; nt < 4; nt++)
                    mma16816(acc[mt][nt], afr[mt], bfr[nt]);
        }
        __syncthreads();
        bf ^= 1;
    }

    // epilogue: scale, fp32 rescue near threshold, blend with exact sa,
    // adjacency mask, write g_s.
    float* S = g_s + (size_t)b * EE * EE;
    const int*   AD = adj + (size_t)b * EE * EE;
    const float* MC = mc  + (size_t)b * EE * EE;
    const float* Qb = g_q + (size_t)b * EE * DD;
    const float* Kb = g_k + (size_t)b * EE * DD;
    const float thr = *thr_p;
    const float inv_sq = 1.0f / 22.627416997969522f;
    const float WIN = 1.5e-3f;   // ~8 sigma of fp16 dot error in s

    const int eq = lane >> 2, er = (lane & 3) * 2;
#pragma unroll
    for (int mt = 0; mt < 4; mt++)
#pragma unroll
        for (int nt = 0; nt < 4; nt++) {
            int n = n0 + wn * 32 + nt * 8 + er;
#pragma unroll
            for (int rh = 0; rh < 2; rh++) {
                int m = m0 + wm * 64 + mt * 16 + eq + rh * 8;
                float2 sa2 = *(const float2*)(S + (size_t)m * EE + n);
                int2   ad2 = *(const int2*)(AD + (size_t)m * EE + n);
                float2 cc2 = *(const float2*)(MC + (size_t)m * EE + n);
                float sv[2] = {acc[mt][nt][rh * 2] * inv_sq,
                               acc[mt][nt][rh * 2 + 1] * inv_sq};
                float sar[2] = {sa2.x, sa2.y};
                float ccr[2] = {cc2.x, cc2.y};
                int   adr[2] = {ad2.x, ad2.y};
                float outr[2];
#pragma unroll
                for (int j = 0; j < 2; j++) {
                    float s = sv[j];
                    // near-threshold: fp32 recompute so the branch matches the
                    // fp32 reference decision (proven R9 mechanism)
                    if (fabsf(s - thr) < WIN)
                        s = dot512(Qb + (size_t)m * DD,
                                   Kb + (size_t)(n + j) * DD) * inv_sq;
                    float sa = sar[j];   // exact fp32 from aux
                    bool merge = (s > thr) && (sa != 0.0f);
                    float co = ccr[j];
                    float r = merge ? (1.0f - co) * s + co * sa : s;
                    if (adr[j] == 0) r = -FLT_MAX;
                    outr[j] = r;
                }
                float2 o = {outr[0], outr[1]};
                *(float2*)(S + (size_t)m * EE + n) = o;
            }
        }
}

// ---------------------------------------------------------------------------
// Kernel 3: row softmax -> fp16 probs in g_s16
// ---------------------------------------------------------------------------
__global__ void __launch_bounds__(256) softmax_kernel()
{
    size_t row = blockIdx.x;
    float* S = g_s + row * EE;
    __half* S16 = g_s16 + row * EE;
    int tid = threadIdx.x;

    float v[8];
    float m = -FLT_MAX;
#pragma unroll
    for (int i = 0; i < 8; i++) {
        v[i] = S[tid + i * 256];
        m = fmaxf(m, v[i]);
    }
    __shared__ float redm[8];
    __shared__ float reds[8];
#pragma unroll
    for (int o = 16; o > 0; o >>= 1) m = fmaxf(m, __shfl_xor_sync(~0u, m, o));
    if ((tid & 31) == 0) redm[tid >> 5] = m;
    __syncthreads();
#pragma unroll
    for (int i = 0; i < 8; i++) m = fmaxf(m, redm[i]);

    float s = 0.f;
#pragma unroll
    for (int i = 0; i < 8; i++) {
        v[i] = __expf(v[i] - m);
        s += v[i];
    }
#pragma unroll
    for (int o = 16; o > 0; o >>= 1) s += __shfl_xor_sync(~0u, s, o);
    if ((tid & 31) == 0) reds[tid >> 5] = s;
    __syncthreads();
    s = 0.f;
#pragma unroll
    for (int i = 0; i < 8; i++) s += reds[i];

    float inv = 1.0f / s;
#pragma unroll
    for (int i = 0; i < 8; i++)
        S16[tid + i * 256] = __float2half_rn(v[i] * inv);
}

// ---------------------------------------------------------------------------
// Kernel 4: out = attn @ v via HMMA, cp.async 2-stage pipeline (proven).
// ---------------------------------------------------------------------------
__global__ void __launch_bounds__(256) av_hmma_kernel(float* __restrict__ out)
{
    extern __shared__ __align__(16) __half dynsm[];

    const int tid = threadIdx.x;
    const int w = tid >> 5, lane = tid & 31;
    const int wm = w & 1, wn = w >> 1;
    const int b = blockIdx.z;
    const int m0 = blockIdx.y * 128, n0 = blockIdx.x * 128;

    const __half* Ag = g_s16 + (size_t)b * EE * EE + (size_t)m0 * EE;
    const __half* Bg = g_vt16 + (size_t)b * DD * EE + (size_t)n0 * EE;
    float* C = out + (size_t)b * EE * DD;

    const uint32_t base = smem_u32(dynsm);

    float acc[4][4][4];
#pragma unroll
    for (int mt = 0; mt < 4; mt++)
#pragma unroll
        for (int nt = 0; nt < 4; nt++)
#pragma unroll
            for (int q = 0; q < 4; q++) acc[mt][nt][q] = 0.f;

    const int lr = tid >> 1;
    const int lu = (tid & 1) * 4;

    const int a_m  = lane & 15;
    const int a_k8 = (lane >> 4) & 1;
    const int b_n  = ((lane >> 4) & 1) * 8 + (lane & 7);
    const int b_k8 = (lane >> 3) & 1;

    auto issue = [&](int k0, int bf) {
        uint32_t sa = base + bf * 32768u;
        uint32_t sb = sa + 16384u;
#pragma unroll
        for (int i = 0; i < 4; i++) {
            int u = lu + i;
            uint32_t off = SW128B((uint32_t)(lr * 128 + u * 16));
            cp16(sa + off, Ag + (size_t)lr * EE + k0 + u * 8);
            cp16(sb + off, Bg + (size_t)lr * EE + k0 + u * 8);
        }
        asm volatile("cp.async.commit_group;" ::: "memory");
    };

    issue(0, 0);
    int bf = 0;

    for (int k0 = 0; k0 < EE; k0 += 64) {
        const bool more = (k0 + 64) < EE;
        if (more) {
            issue(k0 + 64, bf ^ 1);
            asm volatile("cp.async.wait_group 1;" ::: "memory");
        } else {
            asm volatile("cp.async.wait_group 0;" ::: "memory");
        }
        __syncthreads();

        const uint32_t sA_a = base + bf * 32768u;
        const uint32_t sB_a = sA_a + 16384u;
#pragma unroll
        for (int ks = 0; ks < 4; ks++) {
            uint32_t afr[4][4];
#pragma unroll
            for (int mt = 0; mt < 4; mt++) {
                uint32_t off = SW128B((uint32_t)(
                    (wm * 64 + mt * 16 + a_m) * 128 + (ks * 16 + a_k8 * 8) * 2));
                ldm_x4(afr[mt], sA_a + off);
            }
            uint32_t bfr[4][2];
            {
                uint32_t off0 = SW128B((uint32_t)(
                    (wn * 32 + b_n) * 128 + (ks * 16 + b_k8 * 8) * 2));
                uint32_t r[4];
                ldm_x4(r, sB_a + off0);
                bfr[0][0] = r[0]; bfr[0][1] = r[1];
                bfr[1][0] = r[2]; bfr[1][1] = r[3];
                uint32_t off1 = SW128B((uint32_t)(
                    (wn * 32 + 16 + b_n) * 128 + (ks * 16 + b_k8 * 8) * 2));
                ldm_x4(r, sB_a + off1);
                bfr[2][0] = r[0]; bfr[2][1] = r[1];
                bfr[3][0] = r[2]; bfr[3][1] = r[3];
            }
#pragma unroll
            for (int mt = 0; mt < 4; mt++)
#pragma unroll
                for (int nt = 0; nt < 4; nt++)
                    mma16816(acc[mt][nt], afr[mt], bfr[nt]);
        }
        __syncthreads();
        bf ^= 1;
    }

    const int eq = lane >> 2;
    const int er = (lane & 3) * 2;
#pragma unroll
    for (int mt = 0; mt < 4; mt++) {
#pragma unroll
        for (int nt = 0; nt < 4; nt++) {
            int m = m0 + wm * 64 + mt * 16 + eq;
            int n = n0 + wn * 32 + nt * 8 + er;
            float2 lo = {acc[mt][nt][0], acc[mt][nt][1]};
            float2 hi = {acc[mt][nt][2], acc[mt][nt][3]};
            *(float2*)(C + (size_t)m * DD + n) = lo;
            *(float2*)(C + (size_t)(m + 8) * DD + n) = hi;
        }
    }
}

// ---------------------------------------------------------------------------
extern "C" void kernel_launch(void* const* d_in, const int* in_sizes, int n_in,
                              void* d_out, int out_size)
{
    const float* x   = (const float*)d_in[0];
    const float* qa  = (const float*)d_in[1];
    const float* ka  = (const float*)d_in[2];
    const int*   adj = (const int*)  d_in[3];
    const float* mc  = (const float*)d_in[4];
    const float* Wq  = (const float*)d_in[5];
    const float* bq  = (const float*)d_in[6];
    const float* Wk  = (const float*)d_in[7];
    const float* bk  = (const float*)d_in[8];
    const float* Wv  = (const float*)d_in[9];
    const float* bv  = (const float*)d_in[10];
    const float* thr = (const float*)d_in[11];

    static bool attr_set = false;
    if (!attr_set) {
        cudaFuncSetAttribute(av_hmma_kernel,
                             cudaFuncAttributeMaxDynamicSharedMemorySize, 65536);
        cudaFuncSetAttribute(scores_hmma_kernel,
                             cudaFuncAttributeMaxDynamicSharedMemorySize, 65536);
        attr_set = true;
    }

    dim3 blk(256);
    proj_aux_kernel<<<1536 + 2048, blk>>>(x, Wq, bq, Wk, bk, Wv, bv, qa, ka);
    vt_kernel<<<dim3(DD / 32, EE / 32, BB), 256>>>();
    scores_hmma_kernel<<<dim3(EE / 128, EE / 128, BB), blk, 65536>>>(adj, mc, thr);
    softmax_kernel<<<BB * EE, 256>>>();
    av_hmma_kernel<<<dim3(DD / 128, EE / 128, BB), blk, 65536>>>((float*)d_out);
}

// round 15
// speedup vs baseline: 1.8868x; 1.8868x over previous
#include <cuda_runtime.h>
#include <cuda_fp16.h>
#include <math.h>
#include <float.h>
#include <cstdint>

#define BB 8
#define EE 2048
#define DD 512
#define DA 64
#define RESC_MAX (1 << 23)

typedef unsigned long long ull;

// Scratch (static __device__ arrays: allocation-guard safe)
__device__ float g_q[BB * EE * DD];
__device__ float g_k[BB * EE * DD];
__device__ float g_v[BB * EE * DD];
__device__ float g_s[(size_t)BB * EE * EE];
__device__ __half g_s16[(size_t)BB * EE * EE];   // fp16 attn probs
__device__ __half g_vt16[(size_t)BB * DD * EE];  // fp16 V^T, [b][n][k]
__device__ __half g_q16[BB * EE * DD];           // fp16 q (HMMA scores operand)
__device__ __half g_k16[BB * EE * DD];           // fp16 k
__device__ int g_nresc;                          // rescue queue counter
__device__ uint32_t g_resc[RESC_MAX];            // (b<<22)|(m<<11)|n

// smem XOR swizzle for SIMT GEMM tiles
#define SW(r) ((((r) >> 2) & 3) << 3)
// SW128 byte swizzle for 128B-row fp16 tiles (16B-granular)
#define SW128B(o) ((o) ^ (((o) >> 3) & 0x70))

// ---------------------------------------------------------------------------
// helpers
// ---------------------------------------------------------------------------
__device__ __forceinline__ ull pk2(float lo, float hi) {
    ull r;
    asm("mov.b64 %0, {%1,%2};" : "=l"(r) : "f"(lo), "f"(hi));
    return r;
}
__device__ __forceinline__ void ffma2(ull& c, ull a, ull b) {
    asm("fma.rn.f32x2 %0, %1, %2, %0;" : "+l"(c) : "l"(a), "l"(b));
}
__device__ __forceinline__ float2 upk2(ull v) {
    float2 f;
    asm("mov.b64 {%0,%1}, %2;" : "=f"(f.x), "=f"(f.y) : "l"(v));
    return f;
}
__device__ __forceinline__ uint32_t smem_u32(const void* p) {
    uint32_t a;
    asm("{ .reg .u64 t; cvta.to.shared.u64 t, %1; cvt.u32.u64 %0, t; }"
        : "=r"(a) : "l"(p));
    return a;
}
__device__ __forceinline__ void ldm_x4(uint32_t* r, uint32_t addr) {
    asm volatile(
        "ldmatrix.sync.aligned.m8n8.x4.shared.b16 {%0,%1,%2,%3}, [%4];"
        : "=r"(r[0]), "=r"(r[1]), "=r"(r[2]), "=r"(r[3]) : "r"(addr));
}
__device__ __forceinline__ void mma16816(float* d, const uint32_t* a, const uint32_t* b) {
    asm volatile(
        "mma.sync.aligned.m16n8k16.row.col.f32.f16.f16.f32 "
        "{%0,%1,%2,%3}, {%4,%5,%6,%7}, {%8,%9}, {%0,%1,%2,%3};"
        : "+f"(d[0]), "+f"(d[1]), "+f"(d[2]), "+f"(d[3])
        : "r"(a[0]), "r"(a[1]), "r"(a[2]), "r"(a[3]), "r"(b[0]), "r"(b[1]));
}
__device__ __forceinline__ void cp16(uint32_t saddr, const void* gptr) {
    asm volatile("cp.async.cg.shared.global [%0], [%1], 16;"
                 :: "r"(saddr), "l"(gptr) : "memory");
}
__device__ __forceinline__ uint2 h4(float4 v) {
    __half2 a = __floats2half2_rn(v.x, v.y);
    __half2 b = __floats2half2_rn(v.z, v.w);
    uint2 r;
    r.x = *(uint32_t*)&a;
    r.y = *(uint32_t*)&b;
    return r;
}

// serial fp32 dot (queue-overflow fallback only)
__device__ __noinline__ float dot512(const float* __restrict__ a,
                                     const float* __restrict__ b) {
    float s = 0.f;
#pragma unroll 8
    for (int k = 0; k < DD; k += 4) {
        float4 x = *(const float4*)(a + k);
        float4 y = *(const float4*)(b + k);
        s += x.x * y.x + x.y * y.y + x.z * y.z + x.w * y.w;
    }
    return s;
}

// ---------------------------------------------------------------------------
// SIMT 128x128 tile GEMM core (f32x2), double-buffered + swizzled (proven)
// ---------------------------------------------------------------------------
template <bool BT>
__device__ __forceinline__ void mm_tile(
    const float* __restrict__ A, int lda,
    const float* __restrict__ B, int ldb,
    int Ktot, float (*As)[16][128], float (*Bs)[16][128], ull acc[4][8])
{
    const int t = threadIdx.x;
    const int a_c4 = (t & 3) << 2;
    const int a_r  = t >> 2;
    const int b_n4 = (t & 31) << 2;
    const int b_k  = t >> 5;
    const int tx = t & 15, ty = t >> 4;
    const int xsa = a_r ^ SW(a_c4);
    const int xb0 = b_n4 ^ SW(b_k);
    const int xb1 = b_n4 ^ SW(b_k + 8);

    float4 ra0, ra1, rb0, rb1;

    ra0 = *(const float4*)(A + (size_t)a_r * lda + a_c4);
    ra1 = *(const float4*)(A + (size_t)(a_r + 64) * lda + a_c4);
    if (BT) {
        rb0 = *(const float4*)(B + (size_t)a_r * ldb + a_c4);
        rb1 = *(const float4*)(B + (size_t)(a_r + 64) * ldb + a_c4);
    } else {
        rb0 = *(const float4*)(B + (size_t)b_k * ldb + b_n4);
        rb1 = *(const float4*)(B + (size_t)(b_k + 8) * ldb + b_n4);
    }

    int buf = 0;
    {
        As[0][a_c4 + 0][xsa] = ra0.x; As[0][a_c4 + 1][xsa] = ra0.y;
        As[0][a_c4 + 2][xsa] = ra0.z; As[0][a_c4 + 3][xsa] = ra0.w;
        As[0][a_c4 + 0][xsa + 64] = ra1.x; As[0][a_c4 + 1][xsa + 64] = ra1.y;
        As[0][a_c4 + 2][xsa + 64] = ra1.z; As[0][a_c4 + 3][xsa + 64] = ra1.w;
        if (BT) {
            Bs[0][a_c4 + 0][xsa] = rb0.x; Bs[0][a_c4 + 1][xsa] = rb0.y;
            Bs[0][a_c4 + 2][xsa] = rb0.z; Bs[0][a_c4 + 3][xsa] = rb0.w;
            Bs[0][a_c4 + 0][xsa + 64] = rb1.x; Bs[0][a_c4 + 1][xsa + 64] = rb1.y;
            Bs[0][a_c4 + 2][xsa + 64] = rb1.z; Bs[0][a_c4 + 3][xsa + 64] = rb1.w;
        } else {
            *(float4*)&Bs[0][b_k][xb0] = rb0;
            *(float4*)&Bs[0][b_k + 8][xb1] = rb1;
        }
    }
    __syncthreads();

    for (int k0 = 0; k0 < Ktot; k0 += 16) {
        const bool more = (k0 + 16) < Ktot;
        if (more) {
            int kn = k0 + 16;
            ra0 = *(const float4*)(A + (size_t)a_r * lda + kn + a_c4);
            ra1 = *(const float4*)(A + (size_t)(a_r + 64) * lda + kn + a_c4);
            if (BT) {
                rb0 = *(const float4*)(B + (size_t)a_r * ldb + kn + a_c4);
                rb1 = *(const float4*)(B + (size_t)(a_r + 64) * ldb + kn + a_c4);
            } else {
                rb0 = *(const float4*)(B + (size_t)(kn + b_k) * ldb + b_n4);
                rb1 = *(const float4*)(B + (size_t)(kn + b_k + 8) * ldb + b_n4);
            }
        }
#pragma unroll
        for (int kk = 0; kk < 16; kk++) {
            const int xr = SW(kk);
            ulonglong2 ap0 = *(const ulonglong2*)&As[buf][kk][(ty << 2) ^ xr];
            ulonglong2 ap1 = *(const ulonglong2*)&As[buf][kk][64 + ((ty << 2) ^ xr)];
            float4 b0 = *(const float4*)&Bs[buf][kk][(tx << 2) ^ xr];
            float4 b1 = *(const float4*)&Bs[buf][kk][64 + ((tx << 2) ^ xr)];
            ull bb[8] = {pk2(b0.x, b0.x), pk2(b0.y, b0.y),
                         pk2(b0.z, b0.z), pk2(b0.w, b0.w),
                         pk2(b1.x, b1.x), pk2(b1.y, b1.y),
                         pk2(b1.z, b1.z), pk2(b1.w, b1.w)};
            ull aa[4] = {ap0.x, ap0.y, ap1.x, ap1.y};
#pragma unroll
            for (int rp = 0; rp < 4; rp++)
#pragma unroll
                for (int j = 0; j < 8; j++) ffma2(acc[rp][j], aa[rp], bb[j]);
        }
        if (more) {
            int nb = buf ^ 1;
            As[nb][a_c4 + 0][xsa] = ra0.x; As[nb][a_c4 + 1][xsa] = ra0.y;
            As[nb][a_c4 + 2][xsa] = ra0.z; As[nb][a_c4 + 3][xsa] = ra0.w;
            As[nb][a_c4 + 0][xsa + 64] = ra1.x; As[nb][a_c4 + 1][xsa + 64] = ra1.y;
            As[nb][a_c4 + 2][xsa + 64] = ra1.z; As[nb][a_c4 + 3][xsa + 64] = ra1.w;
            if (BT) {
                Bs[nb][a_c4 + 0][xsa] = rb0.x; Bs[nb][a_c4 + 1][xsa] = rb0.y;
                Bs[nb][a_c4 + 2][xsa] = rb0.z; Bs[nb][a_c4 + 3][xsa] = rb0.w;
                Bs[nb][a_c4 + 0][xsa + 64] = rb1.x; Bs[nb][a_c4 + 1][xsa + 64] = rb1.y;
                Bs[nb][a_c4 + 2][xsa + 64] = rb1.z; Bs[nb][a_c4 + 3][xsa + 64] = rb1.w;
            } else {
                *(float4*)&Bs[nb][b_k][xb0] = rb0;
                *(float4*)&Bs[nb][b_k + 8][xb1] = rb1;
            }
        }
        __syncthreads();
        buf ^= 1;
    }
}

__device__ __forceinline__ int pair_row(int rp, int ty) {
    return ((rp >> 1) << 6) + (ty << 2) + ((rp & 1) << 1);
}

// ---------------------------------------------------------------------------
// Kernel 0: reset rescue queue counter
// ---------------------------------------------------------------------------
__global__ void zero_resc_kernel() {
    if (threadIdx.x == 0) g_nresc = 0;
}

// ---------------------------------------------------------------------------
// Kernel 1: MERGED proj + aux-scores (1-D grid).  proj also emits fp16 q/k.
// ---------------------------------------------------------------------------
__global__ void __launch_bounds__(256, 2) proj_aux_kernel(
    const float* __restrict__ x,
    const float* __restrict__ Wq, const float* __restrict__ bq,
    const float* __restrict__ Wk, const float* __restrict__ bk,
    const float* __restrict__ Wv, const float* __restrict__ bv,
    const float* __restrict__ qa, const float* __restrict__ ka)
{
    __shared__ __align__(16) float As[2][16][128];
    __shared__ __align__(16) float Bs[2][16][128];

    int bid = blockIdx.x;
    int tx = threadIdx.x & 15, ty = threadIdx.x >> 4;

    if (bid < 1536) {
        int nx = bid & 3, my = (bid >> 2) & 15, zb = bid >> 6;
        int b = zb / 3, p = zb % 3;
        const float* W    = (p == 0) ? Wq : (p == 1) ? Wk : Wv;
        const float* bias = (p == 0) ? bq : (p == 1) ? bk : bv;
        float* out = ((p == 0) ? g_q : (p == 1) ? g_k : g_v) + (size_t)b * EE * DD;
        __half* out16 = (p == 0) ? (g_q16 + (size_t)b * EE * DD)
                       : (p == 1) ? (g_k16 + (size_t)b * EE * DD) : (__half*)0;

        int m0 = my * 128, n0 = nx * 128;

        ull acc[4][8];
#pragma unroll
        for (int i = 0; i < 4; i++)
#pragma unroll
            for (int j = 0; j < 8; j++) acc[i][j] = 0ull;

        mm_tile<false>(x + (size_t)b * EE * DD + (size_t)m0 * DD, DD,
                       W + n0, DD, DD, As, Bs, acc);

        float4 bias0 = *(const float4*)(bias + n0 + (tx << 2));
        float4 bias1 = *(const float4*)(bias + n0 + 64 + (tx << 2));
        float bb0[4] = {bias0.x, bias0.y, bias0.z, bias0.w};
        float bb1[4] = {bias1.x, bias1.y, bias1.z, bias1.w};
#pragma unroll
        for (int rp = 0; rp < 4; rp++) {
            int r = m0 + pair_row(rp, ty);
            float2 c[8];
#pragma unroll
            for (int j = 0; j < 8; j++) c[j] = upk2(acc[rp][j]);
            float4 lo0 = {c[0].x + bb0[0], c[1].x + bb0[1], c[2].x + bb0[2], c[3].x + bb0[3]};
            float4 lo1 = {c[4].x + bb1[0], c[5].x + bb1[1], c[6].x + bb1[2], c[7].x + bb1[3]};
            float4 hi0 = {c[0].y + bb0[0], c[1].y + bb0[1], c[2].y + bb0[2], c[3].y + bb0[3]};
            float4 hi1 = {c[4].y + bb1[0], c[5].y + bb1[1], c[6].y + bb1[2], c[7].y + bb1[3]};
            *(float4*)(out + (size_t)r * DD + n0 + (tx << 2)) = lo0;
            *(float4*)(out + (size_t)r * DD + n0 + 64 + (tx << 2)) = lo1;
            *(float4*)(out + (size_t)(r + 1) * DD + n0 + (tx << 2)) = hi0;
            *(float4*)(out + (size_t)(r + 1) * DD + n0 + 64 + (tx << 2)) = hi1;
            if (out16) {
                *(uint2*)(out16 + (size_t)r * DD + n0 + (tx << 2)) = h4(lo0);
                *(uint2*)(out16 + (size_t)r * DD + n0 + 64 + (tx << 2)) = h4(lo1);
                *(uint2*)(out16 + (size_t)(r + 1) * DD + n0 + (tx << 2)) = h4(hi0);
                *(uint2*)(out16 + (size_t)(r + 1) * DD + n0 + 64 + (tx << 2)) = h4(hi1);
            }
        }
    } else {
        int a = bid - 1536;
        int fx = a & 15, fy = (a >> 4) & 15, b = a >> 8;
        int m0 = fy * 128, n0 = fx * 128;

        ull acc[4][8];
#pragma unroll
        for (int i = 0; i < 4; i++)
#pragma unroll
            for (int j = 0; j < 8; j++) acc[i][j] = 0ull;

        mm_tile<true>(qa + (size_t)b * EE * DA + (size_t)m0 * DA, DA,
                      ka + (size_t)b * EE * DA + (size_t)n0 * DA, DA,
                      DA, As, Bs, acc);

        float* S = g_s + (size_t)b * EE * EE;
#pragma unroll
        for (int rp = 0; rp < 4; rp++) {
            int r = m0 + pair_row(rp, ty);
            float2 c[8];
#pragma unroll
            for (int j = 0; j < 8; j++) c[j] = upk2(acc[rp][j]);
            float4 lo0 = {c[0].x * 0.125f, c[1].x * 0.125f, c[2].x * 0.125f, c[3].x * 0.125f};
            float4 lo1 = {c[4].x * 0.125f, c[5].x * 0.125f, c[6].x * 0.125f, c[7].x * 0.125f};
            float4 hi0 = {c[0].y * 0.125f, c[1].y * 0.125f, c[2].y * 0.125f, c[3].y * 0.125f};
            float4 hi1 = {c[4].y * 0.125f, c[5].y * 0.125f, c[6].y * 0.125f, c[7].y * 0.125f};
            *(float4*)(S + (size_t)r * EE + n0 + (tx << 2)) = lo0;
            *(float4*)(S + (size_t)r * EE + n0 + 64 + (tx << 2)) = lo1;
            *(float4*)(S + (size_t)(r + 1) * EE + n0 + (tx << 2)) = hi0;
            *(float4*)(S + (size_t)(r + 1) * EE + n0 + 64 + (tx << 2)) = hi1;
        }
    }
}

// ---------------------------------------------------------------------------
// Kernel 1b: V transpose + fp16 convert.  g_v[b][k][n] -> g_vt16[b][n][k]
// ---------------------------------------------------------------------------
__global__ void __launch_bounds__(256) vt_kernel()
{
    __shared__ float tile[32][33];
    int b = blockIdx.z;
    int n0 = blockIdx.x * 32, k0 = blockIdx.y * 32;
    int tx = threadIdx.x & 31, ty = threadIdx.x >> 5;
    const float* V = g_v + (size_t)b * EE * DD;
    __half* VT = g_vt16 + (size_t)b * DD * EE;
#pragma unroll
    for (int i = 0; i < 4; i++)
        tile[ty + i * 8][tx] = V[(size_t)(k0 + ty + i * 8) * DD + n0 + tx];
    __syncthreads();
#pragma unroll
    for (int i = 0; i < 4; i++)
        VT[(size_t)(n0 + ty + i * 8) * EE + k0 + tx] =
            __float2half_rn(tile[tx][ty + i * 8]);
}

// ---------------------------------------------------------------------------
// Kernel 2: main scores via fp16 HMMA (cp.async pipeline).  Near-threshold
// elements are pushed to the rescue queue (no inline dots -> no divergence).
// ---------------------------------------------------------------------------
__global__ void __launch_bounds__(256) scores_hmma_kernel(
    const int* __restrict__ adj, const float* __restrict__ mc,
    const float* __restrict__ thr_p)
{
    extern __shared__ __align__(16) __half dynsm[];

    const int tid = threadIdx.x;
    const int w = tid >> 5, lane = tid & 31;
    const int wm = w & 1, wn = w >> 1;
    const int b = blockIdx.z;
    const int m0 = blockIdx.y * 128, n0 = blockIdx.x * 128;

    const __half* Ag = g_q16 + (size_t)b * EE * DD + (size_t)m0 * DD;
    const __half* Bg = g_k16 + (size_t)b * EE * DD + (size_t)n0 * DD;

    const uint32_t base = smem_u32(dynsm);

    float acc[4][4][4];
#pragma unroll
    for (int mt = 0; mt < 4; mt++)
#pragma unroll
        for (int nt = 0; nt < 4; nt++)
#pragma unroll
            for (int q = 0; q < 4; q++) acc[mt][nt][q] = 0.f;

    const int lr = tid >> 1;
    const int lu = (tid & 1) * 4;

    const int a_m  = lane & 15;
    const int a_k8 = (lane >> 4) & 1;
    const int b_n  = ((lane >> 4) & 1) * 8 + (lane & 7);
    const int b_k8 = (lane >> 3) & 1;

    auto issue = [&](int k0, int bf) {
        uint32_t sa = base + bf * 32768u;
        uint32_t sb = sa + 16384u;
#pragma unroll
        for (int i = 0; i < 4; i++) {
            int u = lu + i;
            uint32_t off = SW128B((uint32_t)(lr * 128 + u * 16));
            cp16(sa + off, Ag + (size_t)lr * DD + k0 + u * 8);
            cp16(sb + off, Bg + (size_t)lr * DD + k0 + u * 8);
        }
        asm volatile("cp.async.commit_group;" ::: "memory");
    };

    issue(0, 0);
    int bf = 0;

    for (int k0 = 0; k0 < DD; k0 += 64) {
        const bool more = (k0 + 64) < DD;
        if (more) {
            issue(k0 + 64, bf ^ 1);
            asm volatile("cp.async.wait_group 1;" ::: "memory");
        } else {
            asm volatile("cp.async.wait_group 0;" ::: "memory");
        }
        __syncthreads();

        const uint32_t sA_a = base + bf * 32768u;
        const uint32_t sB_a = sA_a + 16384u;
#pragma unroll
        for (int ks = 0; ks < 4; ks++) {
            uint32_t afr[4][4];
#pragma unroll
            for (int mt = 0; mt < 4; mt++) {
                uint32_t off = SW128B((uint32_t)(
                    (wm * 64 + mt * 16 + a_m) * 128 + (ks * 16 + a_k8 * 8) * 2));
                ldm_x4(afr[mt], sA_a + off);
            }
            uint32_t bfr[4][2];
            {
                uint32_t off0 = SW128B((uint32_t)(
                    (wn * 32 + b_n) * 128 + (ks * 16 + b_k8 * 8) * 2));
                uint32_t r[4];
                ldm_x4(r, sB_a + off0);
                bfr[0][0] = r[0]; bfr[0][1] = r[1];
                bfr[1][0] = r[2]; bfr[1][1] = r[3];
                uint32_t off1 = SW128B((uint32_t)(
                    (wn * 32 + 16 + b_n) * 128 + (ks * 16 + b_k8 * 8) * 2));
                ldm_x4(r, sB_a + off1);
                bfr[2][0] = r[0]; bfr[2][1] = r[1];
                bfr[3][0] = r[2]; bfr[3][1] = r[3];
            }
#pragma unroll
            for (int mt = 0; mt < 4; mt++)
#pragma unroll
                for (int nt = 0; nt < 4; nt++)
                    mma16816(acc[mt][nt], afr[mt], bfr[nt]);
        }
        __syncthreads();
        bf ^= 1;
    }

    // epilogue: scale; near-threshold -> queue; blend with exact sa; mask.
    float* S = g_s + (size_t)b * EE * EE;
    const int*   AD = adj + (size_t)b * EE * EE;
    const float* MC = mc  + (size_t)b * EE * EE;
    const float* Qb = g_q + (size_t)b * EE * DD;
    const float* Kb = g_k + (size_t)b * EE * DD;
    const float thr = *thr_p;
    const float inv_sq = 1.0f / 22.627416997969522f;
    const float WIN = 1.5e-3f;

    const int eq = lane >> 2, er = (lane & 3) * 2;
#pragma unroll
    for (int mt = 0; mt < 4; mt++)
#pragma unroll
        for (int nt = 0; nt < 4; nt++) {
            int n = n0 + wn * 32 + nt * 8 + er;
#pragma unroll
            for (int rh = 0; rh < 2; rh++) {
                int m = m0 + wm * 64 + mt * 16 + eq + rh * 8;
                float2 sa2 = *(const float2*)(S + (size_t)m * EE + n);
                int2   ad2 = *(const int2*)(AD + (size_t)m * EE + n);
                float2 cc2 = *(const float2*)(MC + (size_t)m * EE + n);
                float sv[2] = {acc[mt][nt][rh * 2] * inv_sq,
                               acc[mt][nt][rh * 2 + 1] * inv_sq};
                float sar[2] = {sa2.x, sa2.y};
                float ccr[2] = {cc2.x, cc2.y};
                int   adr[2] = {ad2.x, ad2.y};
                float outr[2];
#pragma unroll
                for (int j = 0; j < 2; j++) {
                    float s = sv[j];
                    if (fabsf(s - thr) < WIN) {
                        int idx = atomicAdd(&g_nresc, 1);
                        if (idx < RESC_MAX) {
                            g_resc[idx] = ((uint32_t)b << 22) |
                                          ((uint32_t)m << 11) | (uint32_t)(n + j);
                        } else {
                            // overflow fallback: inline fp32 recompute
                            s = dot512(Qb + (size_t)m * DD,
                                       Kb + (size_t)(n + j) * DD) * inv_sq;
                        }
                    }
                    float sa = sar[j];
                    bool merge = (s > thr) && (sa != 0.0f);
                    float co = ccr[j];
                    float r = merge ? (1.0f - co) * s + co * sa : s;
                    if (adr[j] == 0) r = -FLT_MAX;
                    outr[j] = r;
                }
                float2 o = {outr[0], outr[1]};
                *(float2*)(S + (size_t)m * EE + n) = o;
            }
        }
}

// ---------------------------------------------------------------------------
// Kernel 2c: rescue fixer.  One warp per queued element: warp-parallel fp32
// dot512 (decision + value) + dot64 (sa), full epilogue recompute, overwrite.
// ---------------------------------------------------------------------------
__global__ void __launch_bounds__(256) rescue_kernel(
    const float* __restrict__ qa, const float* __restrict__ ka,
    const int* __restrict__ adj, const float* __restrict__ mc,
    const float* __restrict__ thr_p)
{
    const int lane = threadIdx.x & 31;
    const int gw = (blockIdx.x * blockDim.x + threadIdx.x) >> 5;
    const int nw = (gridDim.x * blockDim.x) >> 5;
    const int total = min(g_nresc, RESC_MAX);
    const float thr = *thr_p;
    const float inv_sq = 1.0f / 22.627416997969522f;

    for (int i = gw; i < total; i += nw) {
        uint32_t enc = g_resc[i];
        int n = enc & 2047;
        int m = (enc >> 11) & 2047;
        int b = enc >> 22;

        const float* Q = g_q + ((size_t)b * EE + m) * DD;
        const float* K = g_k + ((size_t)b * EE + n) * DD;
        float p = 0.f;
#pragma unroll
        for (int t = 0; t < 16; t += 4) {
            int idx = lane * 16 + t;
            float4 x = *(const float4*)(Q + idx);
            float4 y = *(const float4*)(K + idx);
            p += x.x * y.x + x.y * y.y + x.z * y.z + x.w * y.w;
        }
#pragma unroll
        for (int o = 16; o > 0; o >>= 1) p += __shfl_xor_sync(~0u, p, o);
        float s = p * inv_sq;

        const float* QA = qa + ((size_t)b * EE + m) * DA;
        const float* KA = ka + ((size_t)b * EE + n) * DA;
        float pa = QA[lane] * KA[lane] + QA[lane + 32] * KA[lane + 32];
#pragma unroll
        for (int o = 16; o > 0; o >>= 1) pa += __shfl_xor_sync(~0u, pa, o);
        float sa = pa * 0.125f;

        if (lane == 0) {
            size_t off = ((size_t)b * EE + m) * EE + n;
            float co = mc[off];
            bool merge = (s > thr) && (sa != 0.0f);
            float r = merge ? (1.0f - co) * s + co * sa : s;
            if (adj[off] == 0) r = -FLT_MAX;
            g_s[off] = r;
        }
    }
}

// ---------------------------------------------------------------------------
// Kernel 3: row softmax -> fp16 probs in g_s16
// ---------------------------------------------------------------------------
__global__ void __launch_bounds__(256) softmax_kernel()
{
    size_t row = blockIdx.x;
    float* S = g_s + row * EE;
    __half* S16 = g_s16 + row * EE;
    int tid = threadIdx.x;

    float v[8];
    float m = -FLT_MAX;
#pragma unroll
    for (int i = 0; i < 8; i++) {
        v[i] = S[tid + i * 256];
        m = fmaxf(m, v[i]);
    }
    __shared__ float redm[8];
    __shared__ float reds[8];
#pragma unroll
    for (int o = 16; o > 0; o >>= 1) m = fmaxf(m, __shfl_xor_sync(~0u, m, o));
    if ((tid & 31) == 0) redm[tid >> 5] = m;
    __syncthreads();
#pragma unroll
    for (int i = 0; i < 8; i++) m = fmaxf(m, redm[i]);

    float s = 0.f;
#pragma unroll
    for (int i = 0; i < 8; i++) {
        v[i] = __expf(v[i] - m);
        s += v[i];
    }
#pragma unroll
    for (int o = 16; o > 0; o >>= 1) s += __shfl_xor_sync(~0u, s, o);
    if ((tid & 31) == 0) reds[tid >> 5] = s;
    __syncthreads();
    s = 0.f;
#pragma unroll
    for (int i = 0; i < 8; i++) s += reds[i];

    float inv = 1.0f / s;
#pragma unroll
    for (int i = 0; i < 8; i++)
        S16[tid + i * 256] = __float2half_rn(v[i] * inv);
}

// ---------------------------------------------------------------------------
// Kernel 4: out = attn @ v via HMMA, cp.async 2-stage pipeline (proven).
// ---------------------------------------------------------------------------
__global__ void __launch_bounds__(256) av_hmma_kernel(float* __restrict__ out)
{
    extern __shared__ __align__(16) __half dynsm[];

    const int tid = threadIdx.x;
    const int w = tid >> 5, lane = tid & 31;
    const int wm = w & 1, wn = w >> 1;
    const int b = blockIdx.z;
    const int m0 = blockIdx.y * 128, n0 = blockIdx.x * 128;

    const __half* Ag = g_s16 + (size_t)b * EE * EE + (size_t)m0 * EE;
    const __half* Bg = g_vt16 + (size_t)b * DD * EE + (size_t)n0 * EE;
    float* C = out + (size_t)b * EE * DD;

    const uint32_t base = smem_u32(dynsm);

    float acc[4][4][4];
#pragma unroll
    for (int mt = 0; mt < 4; mt++)
#pragma unroll
        for (int nt = 0; nt < 4; nt++)
#pragma unroll
            for (int q = 0; q < 4; q++) acc[mt][nt][q] = 0.f;

    const int lr = tid >> 1;
    const int lu = (tid & 1) * 4;

    const int a_m  = lane & 15;
    const int a_k8 = (lane >> 4) & 1;
    const int b_n  = ((lane >> 4) & 1) * 8 + (lane & 7);
    const int b_k8 = (lane >> 3) & 1;

    auto issue = [&](int k0, int bf) {
        uint32_t sa = base + bf * 32768u;
        uint32_t sb = sa + 16384u;
#pragma unroll
        for (int i = 0; i < 4; i++) {
            int u = lu + i;
            uint32_t off = SW128B((uint32_t)(lr * 128 + u * 16));
            cp16(sa + off, Ag + (size_t)lr * EE + k0 + u * 8);
            cp16(sb + off, Bg + (size_t)lr * EE + k0 + u * 8);
        }
        asm volatile("cp.async.commit_group;" ::: "memory");
    };

    issue(0, 0);
    int bf = 0;

    for (int k0 = 0; k0 < EE; k0 += 64) {
        const bool more = (k0 + 64) < EE;
        if (more) {
            issue(k0 + 64, bf ^ 1);
            asm volatile("cp.async.wait_group 1;" ::: "memory");
        } else {
            asm volatile("cp.async.wait_group 0;" ::: "memory");
        }
        __syncthreads();

        const uint32_t sA_a = base + bf * 32768u;
        const uint32_t sB_a = sA_a + 16384u;
#pragma unroll
        for (int ks = 0; ks < 4; ks++) {
            uint32_t afr[4][4];
#pragma unroll
            for (int mt = 0; mt < 4; mt++) {
                uint32_t off = SW128B((uint32_t)(
                    (wm * 64 + mt * 16 + a_m) * 128 + (ks * 16 + a_k8 * 8) * 2));
                ldm_x4(afr[mt], sA_a + off);
            }
            uint32_t bfr[4][2];
            {
                uint32_t off0 = SW128B((uint32_t)(
                    (wn * 32 + b_n) * 128 + (ks * 16 + b_k8 * 8) * 2));
                uint32_t r[4];
                ldm_x4(r, sB_a + off0);
                bfr[0][0] = r[0]; bfr[0][1] = r[1];
                bfr[1][0] = r[2]; bfr[1][1] = r[3];
                uint32_t off1 = SW128B((uint32_t)(
                    (wn * 32 + 16 + b_n) * 128 + (ks * 16 + b_k8 * 8) * 2));
                ldm_x4(r, sB_a + off1);
                bfr[2][0] = r[0]; bfr[2][1] = r[1];
                bfr[3][0] = r[2]; bfr[3][1] = r[3];
            }
#pragma unroll
            for (int mt = 0; mt < 4; mt++)
#pragma unroll
                for (int nt = 0; nt < 4; nt++)
                    mma16816(acc[mt][nt], afr[mt], bfr[nt]);
        }
        __syncthreads();
        bf ^= 1;
    }

    const int eq = lane >> 2;
    const int er = (lane & 3) * 2;
#pragma unroll
    for (int mt = 0; mt < 4; mt++) {
#pragma unroll
        for (int nt = 0; nt < 4; nt++) {
            int m = m0 + wm * 64 + mt * 16 + eq;
            int n = n0 + wn * 32 + nt * 8 + er;
            float2 lo = {acc[mt][nt][0], acc[mt][nt][1]};
            float2 hi = {acc[mt][nt][2], acc[mt][nt][3]};
            *(float2*)(C + (size_t)m * DD + n) = lo;
            *(float2*)(C + (size_t)(m + 8) * DD + n) = hi;
        }
    }
}

// ---------------------------------------------------------------------------
extern "C" void kernel_launch(void* const* d_in, const int* in_sizes, int n_in,
                              void* d_out, int out_size)
{
    const float* x   = (const float*)d_in[0];
    const float* qa  = (const float*)d_in[1];
    const float* ka  = (const float*)d_in[2];
    const int*   adj = (const int*)  d_in[3];
    const float* mc  = (const float*)d_in[4];
    const float* Wq  = (const float*)d_in[5];
    const float* bq  = (const float*)d_in[6];
    const float* Wk  = (const float*)d_in[7];
    const float* bk  = (const float*)d_in[8];
    const float* Wv  = (const float*)d_in[9];
    const float* bv  = (const float*)d_in[10];
    const float* thr = (const float*)d_in[11];

    static bool attr_set = false;
    if (!attr_set) {
        cudaFuncSetAttribute(av_hmma_kernel,
                             cudaFuncAttributeMaxDynamicSharedMemorySize, 65536);
        cudaFuncSetAttribute(scores_hmma_kernel,
                             cudaFuncAttributeMaxDynamicSharedMemorySize, 65536);
        attr_set = true;
    }

    dim3 blk(256);
    zero_resc_kernel<<<1, 32>>>();
    proj_aux_kernel<<<1536 + 2048, blk>>>(x, Wq, bq, Wk, bk, Wv, bv, qa, ka);
    vt_kernel<<<dim3(DD / 32, EE / 32, BB), 256>>>();
    scores_hmma_kernel<<<dim3(EE / 128, EE / 128, BB), blk, 65536>>>(adj, mc, thr);
    rescue_kernel<<<1184, 256>>>(qa, ka, adj, mc, thr);
    softmax_kernel<<<BB * EE, 256>>>();
    av_hmma_kernel<<<dim3(DD / 128, EE / 128, BB), blk, 65536>>>((float*)d_out);
}

// round 16
// speedup vs baseline: 1.8910x; 1.0022x over previous
#include <cuda_runtime.h>
#include <cuda_fp16.h>
#include <math.h>
#include <float.h>
#include <cstdint>

#define BB 8
#define EE 2048
#define DD 512
#define DA 64
#define RESC_MAX (1 << 23)

typedef unsigned long long ull;

// Scratch (static __device__ arrays: allocation-guard safe)
__device__ float g_q[BB * EE * DD];
__device__ float g_k[BB * EE * DD];
__device__ float g_v[BB * EE * DD];
__device__ float g_s[(size_t)BB * EE * EE];
__device__ __half g_s16[(size_t)BB * EE * EE];   // fp16 attn probs
__device__ __half g_vt16[(size_t)BB * DD * EE];  // fp16 V^T, [b][n][k]
__device__ __half g_q16[BB * EE * DD];           // fp16 q (HMMA scores operand)
__device__ __half g_k16[BB * EE * DD];           // fp16 k
__device__ int g_nresc;                          // rescue queue counter
__device__ uint32_t g_resc[RESC_MAX];            // (b<<22)|(m<<11)|n

// smem XOR swizzle for SIMT GEMM tiles
#define SW(r) ((((r) >> 2) & 3) << 3)
// SW128 byte swizzle for 128B-row fp16 tiles (16B-granular)
#define SW128B(o) ((o) ^ (((o) >> 3) & 0x70))

// ---------------------------------------------------------------------------
// helpers
// ---------------------------------------------------------------------------
__device__ __forceinline__ ull pk2(float lo, float hi) {
    ull r;
    asm("mov.b64 %0, {%1,%2};" : "=l"(r) : "f"(lo), "f"(hi));
    return r;
}
__device__ __forceinline__ void ffma2(ull& c, ull a, ull b) {
    asm("fma.rn.f32x2 %0, %1, %2, %0;" : "+l"(c) : "l"(a), "l"(b));
}
__device__ __forceinline__ float2 upk2(ull v) {
    float2 f;
    asm("mov.b64 {%0,%1}, %2;" : "=f"(f.x), "=f"(f.y) : "l"(v));
    return f;
}
__device__ __forceinline__ uint32_t smem_u32(const void* p) {
    uint32_t a;
    asm("{ .reg .u64 t; cvta.to.shared.u64 t, %1; cvt.u32.u64 %0, t; }"
        : "=r"(a) : "l"(p));
    return a;
}
__device__ __forceinline__ void ldm_x4(uint32_t* r, uint32_t addr) {
    asm volatile(
        "ldmatrix.sync.aligned.m8n8.x4.shared.b16 {%0,%1,%2,%3}, [%4];"
        : "=r"(r[0]), "=r"(r[1]), "=r"(r[2]), "=r"(r[3]) : "r"(addr));
}
__device__ __forceinline__ void mma16816(float* d, const uint32_t* a, const uint32_t* b) {
    asm volatile(
        "mma.sync.aligned.m16n8k16.row.col.f32.f16.f16.f32 "
        "{%0,%1,%2,%3}, {%4,%5,%6,%7}, {%8,%9}, {%0,%1,%2,%3};"
        : "+f"(d[0]), "+f"(d[1]), "+f"(d[2]), "+f"(d[3])
        : "r"(a[0]), "r"(a[1]), "r"(a[2]), "r"(a[3]), "r"(b[0]), "r"(b[1]));
}
__device__ __forceinline__ void cp16(uint32_t saddr, const void* gptr) {
    asm volatile("cp.async.cg.shared.global [%0], [%1], 16;"
                 :: "r"(saddr), "l"(gptr) : "memory");
}
__device__ __forceinline__ void cp_commit() {
    asm volatile("cp.async.commit_group;" ::: "memory");
}
__device__ __forceinline__ void cp_wait1() {
    asm volatile("cp.async.wait_group 1;" ::: "memory");
}
__device__ __forceinline__ void cp_wait0() {
    asm volatile("cp.async.wait_group 0;" ::: "memory");
}
__device__ __forceinline__ uint2 h4(float4 v) {
    __half2 a = __floats2half2_rn(v.x, v.y);
    __half2 b = __floats2half2_rn(v.z, v.w);
    uint2 r;
    r.x = *(uint32_t*)&a;
    r.y = *(uint32_t*)&b;
    return r;
}

// serial fp32 dot (queue-overflow fallback only)
__device__ __noinline__ float dot512(const float* __restrict__ a,
                                     const float* __restrict__ b) {
    float s = 0.f;
#pragma unroll 8
    for (int k = 0; k < DD; k += 4) {
        float4 x = *(const float4*)(a + k);
        float4 y = *(const float4*)(b + k);
        s += x.x * y.x + x.y * y.y + x.z * y.z + x.w * y.w;
    }
    return s;
}

// ---------------------------------------------------------------------------
// SIMT 128x128 tile GEMM core (f32x2), double-buffered + swizzled (proven)
// ---------------------------------------------------------------------------
template <bool BT>
__device__ __forceinline__ void mm_tile(
    const float* __restrict__ A, int lda,
    const float* __restrict__ B, int ldb,
    int Ktot, float (*As)[16][128], float (*Bs)[16][128], ull acc[4][8])
{
    const int t = threadIdx.x;
    const int a_c4 = (t & 3) << 2;
    const int a_r  = t >> 2;
    const int b_n4 = (t & 31) << 2;
    const int b_k  = t >> 5;
    const int tx = t & 15, ty = t >> 4;
    const int xsa = a_r ^ SW(a_c4);
    const int xb0 = b_n4 ^ SW(b_k);
    const int xb1 = b_n4 ^ SW(b_k + 8);

    float4 ra0, ra1, rb0, rb1;

    ra0 = *(const float4*)(A + (size_t)a_r * lda + a_c4);
    ra1 = *(const float4*)(A + (size_t)(a_r + 64) * lda + a_c4);
    if (BT) {
        rb0 = *(const float4*)(B + (size_t)a_r * ldb + a_c4);
        rb1 = *(const float4*)(B + (size_t)(a_r + 64) * ldb + a_c4);
    } else {
        rb0 = *(const float4*)(B + (size_t)b_k * ldb + b_n4);
        rb1 = *(const float4*)(B + (size_t)(b_k + 8) * ldb + b_n4);
    }

    int buf = 0;
    {
        As[0][a_c4 + 0][xsa] = ra0.x; As[0][a_c4 + 1][xsa] = ra0.y;
        As[0][a_c4 + 2][xsa] = ra0.z; As[0][a_c4 + 3][xsa] = ra0.w;
        As[0][a_c4 + 0][xsa + 64] = ra1.x; As[0][a_c4 + 1][xsa + 64] = ra1.y;
        As[0][a_c4 + 2][xsa + 64] = ra1.z; As[0][a_c4 + 3][xsa + 64] = ra1.w;
        if (BT) {
            Bs[0][a_c4 + 0][xsa] = rb0.x; Bs[0][a_c4 + 1][xsa] = rb0.y;
            Bs[0][a_c4 + 2][xsa] = rb0.z; Bs[0][a_c4 + 3][xsa] = rb0.w;
            Bs[0][a_c4 + 0][xsa + 64] = rb1.x; Bs[0][a_c4 + 1][xsa + 64] = rb1.y;
            Bs[0][a_c4 + 2][xsa + 64] = rb1.z; Bs[0][a_c4 + 3][xsa + 64] = rb1.w;
        } else {
            *(float4*)&Bs[0][b_k][xb0] = rb0;
            *(float4*)&Bs[0][b_k + 8][xb1] = rb1;
        }
    }
    __syncthreads();

    for (int k0 = 0; k0 < Ktot; k0 += 16) {
        const bool more = (k0 + 16) < Ktot;
        if (more) {
            int kn = k0 + 16;
            ra0 = *(const float4*)(A + (size_t)a_r * lda + kn + a_c4);
            ra1 = *(const float4*)(A + (size_t)(a_r + 64) * lda + kn + a_c4);
            if (BT) {
                rb0 = *(const float4*)(B + (size_t)a_r * ldb + kn + a_c4);
                rb1 = *(const float4*)(B + (size_t)(a_r + 64) * ldb + kn + a_c4);
            } else {
                rb0 = *(const float4*)(B + (size_t)(kn + b_k) * ldb + b_n4);
                rb1 = *(const float4*)(B + (size_t)(kn + b_k + 8) * ldb + b_n4);
            }
        }
#pragma unroll
        for (int kk = 0; kk < 16; kk++) {
            const int xr = SW(kk);
            ulonglong2 ap0 = *(const ulonglong2*)&As[buf][kk][(ty << 2) ^ xr];
            ulonglong2 ap1 = *(const ulonglong2*)&As[buf][kk][64 + ((ty << 2) ^ xr)];
            float4 b0 = *(const float4*)&Bs[buf][kk][(tx << 2) ^ xr];
            float4 b1 = *(const float4*)&Bs[buf][kk][64 + ((tx << 2) ^ xr)];
            ull bb[8] = {pk2(b0.x, b0.x), pk2(b0.y, b0.y),
                         pk2(b0.z, b0.z), pk2(b0.w, b0.w),
                         pk2(b1.x, b1.x), pk2(b1.y, b1.y),
                         pk2(b1.z, b1.z), pk2(b1.w, b1.w)};
            ull aa[4] = {ap0.x, ap0.y, ap1.x, ap1.y};
#pragma unroll
            for (int rp = 0; rp < 4; rp++)
#pragma unroll
                for (int j = 0; j < 8; j++) ffma2(acc[rp][j], aa[rp], bb[j]);
        }
        if (more) {
            int nb = buf ^ 1;
            As[nb][a_c4 + 0][xsa] = ra0.x; As[nb][a_c4 + 1][xsa] = ra0.y;
            As[nb][a_c4 + 2][xsa] = ra0.z; As[nb][a_c4 + 3][xsa] = ra0.w;
            As[nb][a_c4 + 0][xsa + 64] = ra1.x; As[nb][a_c4 + 1][xsa + 64] = ra1.y;
            As[nb][a_c4 + 2][xsa + 64] = ra1.z; As[nb][a_c4 + 3][xsa + 64] = ra1.w;
            if (BT) {
                Bs[nb][a_c4 + 0][xsa] = rb0.x; Bs[nb][a_c4 + 1][xsa] = rb0.y;
                Bs[nb][a_c4 + 2][xsa] = rb0.z; Bs[nb][a_c4 + 3][xsa] = rb0.w;
                Bs[nb][a_c4 + 0][xsa + 64] = rb1.x; Bs[nb][a_c4 + 1][xsa + 64] = rb1.y;
                Bs[nb][a_c4 + 2][xsa + 64] = rb1.z; Bs[nb][a_c4 + 3][xsa + 64] = rb1.w;
            } else {
                *(float4*)&Bs[nb][b_k][xb0] = rb0;
                *(float4*)&Bs[nb][b_k + 8][xb1] = rb1;
            }
        }
        __syncthreads();
        buf ^= 1;
    }
}

__device__ __forceinline__ int pair_row(int rp, int ty) {
    return ((rp >> 1) << 6) + (ty << 2) + ((rp & 1) << 1);
}

// ---------------------------------------------------------------------------
// Kernel 0: reset rescue queue counter
// ---------------------------------------------------------------------------
__global__ void zero_resc_kernel() {
    if (threadIdx.x == 0) g_nresc = 0;
}

// ---------------------------------------------------------------------------
// Kernel 1: MERGED proj + aux-scores (1-D grid).  proj also emits fp16 q/k.
// ---------------------------------------------------------------------------
__global__ void __launch_bounds__(256, 2) proj_aux_kernel(
    const float* __restrict__ x,
    const float* __restrict__ Wq, const float* __restrict__ bq,
    const float* __restrict__ Wk, const float* __restrict__ bk,
    const float* __restrict__ Wv, const float* __restrict__ bv,
    const float* __restrict__ qa, const float* __restrict__ ka)
{
    __shared__ __align__(16) float As[2][16][128];
    __shared__ __align__(16) float Bs[2][16][128];

    int bid = blockIdx.x;
    int tx = threadIdx.x & 15, ty = threadIdx.x >> 4;

    if (bid < 1536) {
        int nx = bid & 3, my = (bid >> 2) & 15, zb = bid >> 6;
        int b = zb / 3, p = zb % 3;
        const float* W    = (p == 0) ? Wq : (p == 1) ? Wk : Wv;
        const float* bias = (p == 0) ? bq : (p == 1) ? bk : bv;
        float* out = ((p == 0) ? g_q : (p == 1) ? g_k : g_v) + (size_t)b * EE * DD;
        __half* out16 = (p == 0) ? (g_q16 + (size_t)b * EE * DD)
                       : (p == 1) ? (g_k16 + (size_t)b * EE * DD) : (__half*)0;

        int m0 = my * 128, n0 = nx * 128;

        ull acc[4][8];
#pragma unroll
        for (int i = 0; i < 4; i++)
#pragma unroll
            for (int j = 0; j < 8; j++) acc[i][j] = 0ull;

        mm_tile<false>(x + (size_t)b * EE * DD + (size_t)m0 * DD, DD,
                       W + n0, DD, DD, As, Bs, acc);

        float4 bias0 = *(const float4*)(bias + n0 + (tx << 2));
        float4 bias1 = *(const float4*)(bias + n0 + 64 + (tx << 2));
        float bb0[4] = {bias0.x, bias0.y, bias0.z, bias0.w};
        float bb1[4] = {bias1.x, bias1.y, bias1.z, bias1.w};
#pragma unroll
        for (int rp = 0; rp < 4; rp++) {
            int r = m0 + pair_row(rp, ty);
            float2 c[8];
#pragma unroll
            for (int j = 0; j < 8; j++) c[j] = upk2(acc[rp][j]);
            float4 lo0 = {c[0].x + bb0[0], c[1].x + bb0[1], c[2].x + bb0[2], c[3].x + bb0[3]};
            float4 lo1 = {c[4].x + bb1[0], c[5].x + bb1[1], c[6].x + bb1[2], c[7].x + bb1[3]};
            float4 hi0 = {c[0].y + bb0[0], c[1].y + bb0[1], c[2].y + bb0[2], c[3].y + bb0[3]};
            float4 hi1 = {c[4].y + bb1[0], c[5].y + bb1[1], c[6].y + bb1[2], c[7].y + bb1[3]};
            *(float4*)(out + (size_t)r * DD + n0 + (tx << 2)) = lo0;
            *(float4*)(out + (size_t)r * DD + n0 + 64 + (tx << 2)) = lo1;
            *(float4*)(out + (size_t)(r + 1) * DD + n0 + (tx << 2)) = hi0;
            *(float4*)(out + (size_t)(r + 1) * DD + n0 + 64 + (tx << 2)) = hi1;
            if (out16) {
                *(uint2*)(out16 + (size_t)r * DD + n0 + (tx << 2)) = h4(lo0);
                *(uint2*)(out16 + (size_t)r * DD + n0 + 64 + (tx << 2)) = h4(lo1);
                *(uint2*)(out16 + (size_t)(r + 1) * DD + n0 + (tx << 2)) = h4(hi0);
                *(uint2*)(out16 + (size_t)(r + 1) * DD + n0 + 64 + (tx << 2)) = h4(hi1);
            }
        }
    } else {
        int a = bid - 1536;
        int fx = a & 15, fy = (a >> 4) & 15, b = a >> 8;
        int m0 = fy * 128, n0 = fx * 128;

        ull acc[4][8];
#pragma unroll
        for (int i = 0; i < 4; i++)
#pragma unroll
            for (int j = 0; j < 8; j++) acc[i][j] = 0ull;

        mm_tile<true>(qa + (size_t)b * EE * DA + (size_t)m0 * DA, DA,
                      ka + (size_t)b * EE * DA + (size_t)n0 * DA, DA,
                      DA, As, Bs, acc);

        float* S = g_s + (size_t)b * EE * EE;
#pragma unroll
        for (int rp = 0; rp < 4; rp++) {
            int r = m0 + pair_row(rp, ty);
            float2 c[8];
#pragma unroll
            for (int j = 0; j < 8; j++) c[j] = upk2(acc[rp][j]);
            float4 lo0 = {c[0].x * 0.125f, c[1].x * 0.125f, c[2].x * 0.125f, c[3].x * 0.125f};
            float4 lo1 = {c[4].x * 0.125f, c[5].x * 0.125f, c[6].x * 0.125f, c[7].x * 0.125f};
            float4 hi0 = {c[0].y * 0.125f, c[1].y * 0.125f, c[2].y * 0.125f, c[3].y * 0.125f};
            float4 hi1 = {c[4].y * 0.125f, c[5].y * 0.125f, c[6].y * 0.125f, c[7].y * 0.125f};
            *(float4*)(S + (size_t)r * EE + n0 + (tx << 2)) = lo0;
            *(float4*)(S + (size_t)r * EE + n0 + 64 + (tx << 2)) = lo1;
            *(float4*)(S + (size_t)(r + 1) * EE + n0 + (tx << 2)) = hi0;
            *(float4*)(S + (size_t)(r + 1) * EE + n0 + 64 + (tx << 2)) = hi1;
        }
    }
}

// ---------------------------------------------------------------------------
// Kernel 1b: V transpose + fp16 convert.  g_v[b][k][n] -> g_vt16[b][n][k]
// ---------------------------------------------------------------------------
__global__ void __launch_bounds__(256) vt_kernel()
{
    __shared__ float tile[32][33];
    int b = blockIdx.z;
    int n0 = blockIdx.x * 32, k0 = blockIdx.y * 32;
    int tx = threadIdx.x & 31, ty = threadIdx.x >> 5;
    const float* V = g_v + (size_t)b * EE * DD;
    __half* VT = g_vt16 + (size_t)b * DD * EE;
#pragma unroll
    for (int i = 0; i < 4; i++)
        tile[ty + i * 8][tx] = V[(size_t)(k0 + ty + i * 8) * DD + n0 + tx];
    __syncthreads();
#pragma unroll
    for (int i = 0; i < 4; i++)
        VT[(size_t)(n0 + ty + i * 8) * EE + k0 + tx] =
            __float2half_rn(tile[tx][ty + i * 8]);
}

// ---------------------------------------------------------------------------
// Kernel 2: main scores via fp16 HMMA, 3-stage cp.async pipeline, one
// __syncthreads per chunk.  Near-threshold -> rescue queue.
// Dyn smem: 3 x (16K A + 16K B) = 96 KB.
// ---------------------------------------------------------------------------
__global__ void __launch_bounds__(256) scores_hmma_kernel(
    const int* __restrict__ adj, const float* __restrict__ mc,
    const float* __restrict__ thr_p)
{
    extern __shared__ __align__(16) __half dynsm[];

    const int tid = threadIdx.x;
    const int w = tid >> 5, lane = tid & 31;
    const int wm = w & 1, wn = w >> 1;
    const int b = blockIdx.z;
    const int m0 = blockIdx.y * 128, n0 = blockIdx.x * 128;

    const __half* Ag = g_q16 + (size_t)b * EE * DD + (size_t)m0 * DD;
    const __half* Bg = g_k16 + (size_t)b * EE * DD + (size_t)n0 * DD;

    const uint32_t base = smem_u32(dynsm);

    float acc[4][4][4];
#pragma unroll
    for (int mt = 0; mt < 4; mt++)
#pragma unroll
        for (int nt = 0; nt < 4; nt++)
#pragma unroll
            for (int q = 0; q < 4; q++) acc[mt][nt][q] = 0.f;

    const int lr = tid >> 1;
    const int lu = (tid & 1) * 4;

    const int a_m  = lane & 15;
    const int a_k8 = (lane >> 4) & 1;
    const int b_n  = ((lane >> 4) & 1) * 8 + (lane & 7);
    const int b_k8 = (lane >> 3) & 1;

    auto issue = [&](int ci) {
        int bf = ci % 3;
        int k0 = ci * 64;
        uint32_t sa = base + bf * 32768u;
        uint32_t sb = sa + 16384u;
#pragma unroll
        for (int i = 0; i < 4; i++) {
            int u = lu + i;
            uint32_t off = SW128B((uint32_t)(lr * 128 + u * 16));
            cp16(sa + off, Ag + (size_t)lr * DD + k0 + u * 8);
            cp16(sb + off, Bg + (size_t)lr * DD + k0 + u * 8);
        }
        cp_commit();
    };

    const int NC = DD / 64;  // 8 chunks
    issue(0);
    issue(1);

    for (int ci = 0; ci < NC; ci++) {
        if (ci + 1 < NC) cp_wait1(); else cp_wait0();
        __syncthreads();
        if (ci + 2 < NC) issue(ci + 2);

        const uint32_t sA_a = base + (ci % 3) * 32768u;
        const uint32_t sB_a = sA_a + 16384u;
#pragma unroll
        for (int ks = 0; ks < 4; ks++) {
            uint32_t afr[4][4];
#pragma unroll
            for (int mt = 0; mt < 4; mt++) {
                uint32_t off = SW128B((uint32_t)(
                    (wm * 64 + mt * 16 + a_m) * 128 + (ks * 16 + a_k8 * 8) * 2));
                ldm_x4(afr[mt], sA_a + off);
            }
            uint32_t bfr[4][2];
            {
                uint32_t off0 = SW128B((uint32_t)(
                    (wn * 32 + b_n) * 128 + (ks * 16 + b_k8 * 8) * 2));
                uint32_t r[4];
                ldm_x4(r, sB_a + off0);
                bfr[0][0] = r[0]; bfr[0][1] = r[1];
                bfr[1][0] = r[2]; bfr[1][1] = r[3];
                uint32_t off1 = SW128B((uint32_t)(
                    (wn * 32 + 16 + b_n) * 128 + (ks * 16 + b_k8 * 8) * 2));
                ldm_x4(r, sB_a + off1);
                bfr[2][0] = r[0]; bfr[2][1] = r[1];
                bfr[3][0] = r[2]; bfr[3][1] = r[3];
            }
#pragma unroll
            for (int mt = 0; mt < 4; mt++)
#pragma unroll
                for (int nt = 0; nt < 4; nt++)
                    mma16816(acc[mt][nt], afr[mt], bfr[nt]);
        }
    }

    // epilogue: scale; near-threshold -> queue; blend with exact sa; mask.
    float* S = g_s + (size_t)b * EE * EE;
    const int*   AD = adj + (size_t)b * EE * EE;
    const float* MC = mc  + (size_t)b * EE * EE;
    const float* Qb = g_q + (size_t)b * EE * DD;
    const float* Kb = g_k + (size_t)b * EE * DD;
    const float thr = *thr_p;
    const float inv_sq = 1.0f / 22.627416997969522f;
    const float WIN = 1.5e-3f;

    const int eq = lane >> 2, er = (lane & 3) * 2;
#pragma unroll
    for (int mt = 0; mt < 4; mt++)
#pragma unroll
        for (int nt = 0; nt < 4; nt++) {
            int n = n0 + wn * 32 + nt * 8 + er;
#pragma unroll
            for (int rh = 0; rh < 2; rh++) {
                int m = m0 + wm * 64 + mt * 16 + eq + rh * 8;
                float2 sa2 = *(const float2*)(S + (size_t)m * EE + n);
                int2   ad2 = *(const int2*)(AD + (size_t)m * EE + n);
                float2 cc2 = *(const float2*)(MC + (size_t)m * EE + n);
                float sv[2] = {acc[mt][nt][rh * 2] * inv_sq,
                               acc[mt][nt][rh * 2 + 1] * inv_sq};
                float sar[2] = {sa2.x, sa2.y};
                float ccr[2] = {cc2.x, cc2.y};
                int   adr[2] = {ad2.x, ad2.y};
                float outr[2];
#pragma unroll
                for (int j = 0; j < 2; j++) {
                    float s = sv[j];
                    if (fabsf(s - thr) < WIN) {
                        int idx = atomicAdd(&g_nresc, 1);
                        if (idx < RESC_MAX) {
                            g_resc[idx] = ((uint32_t)b << 22) |
                                          ((uint32_t)m << 11) | (uint32_t)(n + j);
                        } else {
                            s = dot512(Qb + (size_t)m * DD,
                                       Kb + (size_t)(n + j) * DD) * inv_sq;
                        }
                    }
                    float sa = sar[j];
                    bool merge = (s > thr) && (sa != 0.0f);
                    float co = ccr[j];
                    float r = merge ? (1.0f - co) * s + co * sa : s;
                    if (adr[j] == 0) r = -FLT_MAX;
                    outr[j] = r;
                }
                float2 o = {outr[0], outr[1]};
                *(float2*)(S + (size_t)m * EE + n) = o;
            }
        }
}

// ---------------------------------------------------------------------------
// Kernel 2c: rescue fixer.  One warp per queued element.
// ---------------------------------------------------------------------------
__global__ void __launch_bounds__(256) rescue_kernel(
    const float* __restrict__ qa, const float* __restrict__ ka,
    const int* __restrict__ adj, const float* __restrict__ mc,
    const float* __restrict__ thr_p)
{
    const int lane = threadIdx.x & 31;
    const int gw = (blockIdx.x * blockDim.x + threadIdx.x) >> 5;
    const int nw = (gridDim.x * blockDim.x) >> 5;
    const int total = min(g_nresc, RESC_MAX);
    const float thr = *thr_p;
    const float inv_sq = 1.0f / 22.627416997969522f;

    for (int i = gw; i < total; i += nw) {
        uint32_t enc = g_resc[i];
        int n = enc & 2047;
        int m = (enc >> 11) & 2047;
        int b = enc >> 22;

        const float* Q = g_q + ((size_t)b * EE + m) * DD;
        const float* K = g_k + ((size_t)b * EE + n) * DD;
        float p = 0.f;
#pragma unroll
        for (int t = 0; t < 16; t += 4) {
            int idx = lane * 16 + t;
            float4 x = *(const float4*)(Q + idx);
            float4 y = *(const float4*)(K + idx);
            p += x.x * y.x + x.y * y.y + x.z * y.z + x.w * y.w;
        }
#pragma unroll
        for (int o = 16; o > 0; o >>= 1) p += __shfl_xor_sync(~0u, p, o);
        float s = p * inv_sq;

        const float* QA = qa + ((size_t)b * EE + m) * DA;
        const float* KA = ka + ((size_t)b * EE + n) * DA;
        float pa = QA[lane] * KA[lane] + QA[lane + 32] * KA[lane + 32];
#pragma unroll
        for (int o = 16; o > 0; o >>= 1) pa += __shfl_xor_sync(~0u, pa, o);
        float sa = pa * 0.125f;

        if (lane == 0) {
            size_t off = ((size_t)b * EE + m) * EE + n;
            float co = mc[off];
            bool merge = (s > thr) && (sa != 0.0f);
            float r = merge ? (1.0f - co) * s + co * sa : s;
            if (adj[off] == 0) r = -FLT_MAX;
            g_s[off] = r;
        }
    }
}

// ---------------------------------------------------------------------------
// Kernel 3: row softmax -> fp16 probs in g_s16
// ---------------------------------------------------------------------------
__global__ void __launch_bounds__(256) softmax_kernel()
{
    size_t row = blockIdx.x;
    float* S = g_s + row * EE;
    __half* S16 = g_s16 + row * EE;
    int tid = threadIdx.x;

    float v[8];
    float m = -FLT_MAX;
#pragma unroll
    for (int i = 0; i < 8; i++) {
        v[i] = S[tid + i * 256];
        m = fmaxf(m, v[i]);
    }
    __shared__ float redm[8];
    __shared__ float reds[8];
#pragma unroll
    for (int o = 16; o > 0; o >>= 1) m = fmaxf(m, __shfl_xor_sync(~0u, m, o));
    if ((tid & 31) == 0) redm[tid >> 5] = m;
    __syncthreads();
#pragma unroll
    for (int i = 0; i < 8; i++) m = fmaxf(m, redm[i]);

    float s = 0.f;
#pragma unroll
    for (int i = 0; i < 8; i++) {
        v[i] = __expf(v[i] - m);
        s += v[i];
    }
#pragma unroll
    for (int o = 16; o > 0; o >>= 1) s += __shfl_xor_sync(~0u, s, o);
    if ((tid & 31) == 0) reds[tid >> 5] = s;
    __syncthreads();
    s = 0.f;
#pragma unroll
    for (int i = 0; i < 8; i++) s += reds[i];

    float inv = 1.0f / s;
#pragma unroll
    for (int i = 0; i < 8; i++)
        S16[tid + i * 256] = __float2half_rn(v[i] * inv);
}

// ---------------------------------------------------------------------------
// Kernel 4: out = attn @ v via HMMA, 3-stage cp.async pipeline, one sync.
// ---------------------------------------------------------------------------
__global__ void __launch_bounds__(256) av_hmma_kernel(float* __restrict__ out)
{
    extern __shared__ __align__(16) __half dynsm[];

    const int tid = threadIdx.x;
    const int w = tid >> 5, lane = tid & 31;
    const int wm = w & 1, wn = w >> 1;
    const int b = blockIdx.z;
    const int m0 = blockIdx.y * 128, n0 = blockIdx.x * 128;

    const __half* Ag = g_s16 + (size_t)b * EE * EE + (size_t)m0 * EE;
    const __half* Bg = g_vt16 + (size_t)b * DD * EE + (size_t)n0 * EE;
    float* C = out + (size_t)b * EE * DD;

    const uint32_t base = smem_u32(dynsm);

    float acc[4][4][4];
#pragma unroll
    for (int mt = 0; mt < 4; mt++)
#pragma unroll
        for (int nt = 0; nt < 4; nt++)
#pragma unroll
            for (int q = 0; q < 4; q++) acc[mt][nt][q] = 0.f;

    const int lr = tid >> 1;
    const int lu = (tid & 1) * 4;

    const int a_m  = lane & 15;
    const int a_k8 = (lane >> 4) & 1;
    const int b_n  = ((lane >> 4) & 1) * 8 + (lane & 7);
    const int b_k8 = (lane >> 3) & 1;

    auto issue = [&](int ci) {
        int bf = ci % 3;
        int k0 = ci * 64;
        uint32_t sa = base + bf * 32768u;
        uint32_t sb = sa + 16384u;
#pragma unroll
        for (int i = 0; i < 4; i++) {
            int u = lu + i;
            uint32_t off = SW128B((uint32_t)(lr * 128 + u * 16));
            cp16(sa + off, Ag + (size_t)lr * EE + k0 + u * 8);
            cp16(sb + off, Bg + (size_t)lr * EE + k0 + u * 8);
        }
        cp_commit();
    };

    const int NC = EE / 64;  // 32 chunks
    issue(0);
    issue(1);

    for (int ci = 0; ci < NC; ci++) {
        if (ci + 1 < NC) cp_wait1(); else cp_wait0();
        __syncthreads();
        if (ci + 2 < NC) issue(ci + 2);

        const uint32_t sA_a = base + (ci % 3) * 32768u;
        const uint32_t sB_a = sA_a + 16384u;
#pragma unroll
        for (int ks = 0; ks < 4; ks++) {
            uint32_t afr[4][4];
#pragma unroll
            for (int mt = 0; mt < 4; mt++) {
                uint32_t off = SW128B((uint32_t)(
                    (wm * 64 + mt * 16 + a_m) * 128 + (ks * 16 + a_k8 * 8) * 2));
                ldm_x4(afr[mt], sA_a + off);
            }
            uint32_t bfr[4][2];
            {
                uint32_t off0 = SW128B((uint32_t)(
                    (wn * 32 + b_n) * 128 + (ks * 16 + b_k8 * 8) * 2));
                uint32_t r[4];
                ldm_x4(r, sB_a + off0);
                bfr[0][0] = r[0]; bfr[0][1] = r[1];
                bfr[1][0] = r[2]; bfr[1][1] = r[3];
                uint32_t off1 = SW128B((uint32_t)(
                    (wn * 32 + 16 + b_n) * 128 + (ks * 16 + b_k8 * 8) * 2));
                ldm_x4(r, sB_a + off1);
                bfr[2][0] = r[0]; bfr[2][1] = r[1];
                bfr[3][0] = r[2]; bfr[3][1] = r[3];
            }
#pragma unroll
            for (int mt = 0; mt < 4; mt++)
#pragma unroll
                for (int nt = 0; nt < 4; nt++)
                    mma16816(acc[mt][nt], afr[mt], bfr[nt]);
        }
    }

    const int eq = lane >> 2;
    const int er = (lane & 3) * 2;
#pragma unroll
    for (int mt = 0; mt < 4; mt++) {
#pragma unroll
        for (int nt = 0; nt < 4; nt++) {
            int m = m0 + wm * 64 + mt * 16 + eq;
            int n = n0 + wn * 32 + nt * 8 + er;
            float2 lo = {acc[mt][nt][0], acc[mt][nt][1]};
            float2 hi = {acc[mt][nt][2], acc[mt][nt][3]};
            *(float2*)(C + (size_t)m * DD + n) = lo;
            *(float2*)(C + (size_t)(m + 8) * DD + n) = hi;
        }
    }
}

// ---------------------------------------------------------------------------
extern "C" void kernel_launch(void* const* d_in, const int* in_sizes, int n_in,
                              void* d_out, int out_size)
{
    const float* x   = (const float*)d_in[0];
    const float* qa  = (const float*)d_in[1];
    const float* ka  = (const float*)d_in[2];
    const int*   adj = (const int*)  d_in[3];
    const float* mc  = (const float*)d_in[4];
    const float* Wq  = (const float*)d_in[5];
    const float* bq  = (const float*)d_in[6];
    const float* Wk  = (const float*)d_in[7];
    const float* bk  = (const float*)d_in[8];
    const float* Wv  = (const float*)d_in[9];
    const float* bv  = (const float*)d_in[10];
    const float* thr = (const float*)d_in[11];

    static bool attr_set = false;
    if (!attr_set) {
        cudaFuncSetAttribute(av_hmma_kernel,
                             cudaFuncAttributeMaxDynamicSharedMemorySize, 98304);
        cudaFuncSetAttribute(scores_hmma_kernel,
                             cudaFuncAttributeMaxDynamicSharedMemorySize, 98304);
        attr_set = true;
    }

    dim3 blk(256);
    zero_resc_kernel<<<1, 32>>>();
    proj_aux_kernel<<<1536 + 2048, blk>>>(x, Wq, bq, Wk, bk, Wv, bv, qa, ka);
    vt_kernel<<<dim3(DD / 32, EE / 32, BB), 256>>>();
    scores_hmma_kernel<<<dim3(EE / 128, EE / 128, BB), blk, 98304>>>(adj, mc, thr);
    rescue_kernel<<<1184, 256>>>(qa, ka, adj, mc, thr);
    softmax_kernel<<<BB * EE, 256>>>();
    av_hmma_kernel<<<dim3(DD / 128, EE / 128, BB), blk, 98304>>>((float*)d_out);
}